// round 15
// baseline (speedup 1.0000x reference)
#include <cuda_runtime.h>
#include <math.h>

#define D 128
#define G 256
#define BMAX 8192
#define CHUNK 8   // nodes per warp, front-batched streaming loads

__device__ float g_w[D];        // Wp @ We[:G]
__device__ float g_c;           // bp . We[:G]
__device__ float g_accum[BMAX]; // zero at module load; combine re-zeroes after use
__device__ float g_src[BMAX];   // src-embed dot per graph

__device__ __forceinline__ float warp_sum(float v) {
    #pragma unroll
    for (int off = 16; off > 0; off >>= 1)
        v += __shfl_xor_sync(0xffffffffu, v, off);
    return v;
}

// ---------------------------------------------------------------------------
// Kernel 1: fold Wp/bp into We's graph-embed half.
// warps 0..127 -> g_w[warp]; warp 128 -> g_c.
// ---------------------------------------------------------------------------
__global__ void dgmg_precompute(const float* __restrict__ Wp,
                                const float* __restrict__ bp,
                                const float* __restrict__ We) {
    int gt   = blockIdx.x * blockDim.x + threadIdx.x;
    int gw   = gt >> 5;
    int lane = gt & 31;
    if (gw < D) {
        const float* row = Wp + (size_t)gw * G;
        float s = 0.0f;
        #pragma unroll
        for (int i = 0; i < G / 32; i++) {
            int idx = lane + 32 * i;
            s += row[idx] * We[idx];
        }
        s = warp_sum(s);
        if (lane == 0) g_w[gw] = s;
    } else if (gw == D) {
        float s = 0.0f;
        #pragma unroll
        for (int i = 0; i < G / 32; i++) {
            int idx = lane + 32 * i;
            s += bp[idx] * We[idx];
        }
        s = warp_sum(s);
        if (lane == 0) g_c = s;
    }
}

// ---------------------------------------------------------------------------
// Kernel 2: src-embed gather (head of grid) + node stream (rest of grid).
// 256 threads/block (8 warps), CHUNK=8 nodes/warp: 8 front-batched __ldcs
// LDG.128 per lane (4KB in flight per warp). Exact-chunk fast path avoids all
// clamping when start+CHUNK <= N.
// ---------------------------------------------------------------------------
__global__ void __launch_bounds__(256)
dgmg_main(const float* __restrict__ hv,
          const float* __restrict__ Wg,
          const float* __restrict__ bg,
          const int*   __restrict__ seg,
          const float* __restrict__ We,
          const int*   __restrict__ last_idx,
          int N, int B, int srcBlocks) {
    const int lane   = threadIdx.x & 31;
    const int warpIB = threadIdx.x >> 5;

    if (blockIdx.x < (unsigned)srcBlocks) {
        // ---- src-embed gather ----
        const int b = blockIdx.x * 8 + warpIB;
        if (b >= B) return;
        const int li = __ldg(last_idx + b);
        const float4 h  = reinterpret_cast<const float4*>(hv + (size_t)li * D)[lane];
        const float4 we = reinterpret_cast<const float4*>(We + G)[lane];
        float d = h.x * we.x + h.y * we.y + h.z * we.z + h.w * we.w;
        d = warp_sum(d);
        if (lane == 0) g_src[b] = d;
        return;
    }

    // ---- node streaming ----
    const int wid   = (blockIdx.x - srcBlocks) * 8 + warpIB;
    const int start = wid * CHUNK;
    if (start >= N) return;

    const float4* hv4  = reinterpret_cast<const float4*>(hv);
    const float4* base = hv4 + (size_t)start * 32 + lane;

    float4 r[CHUNK];
    int    segv;
    int    cnt;
    if (start + CHUNK <= N) {
        // exact fast path: no clamps, pure streaming loads
        cnt = CHUNK;
        #pragma unroll
        for (int j = 0; j < CHUNK; j++)
            r[j] = __ldcs(base + (size_t)j * 32);
        segv = __ldg(seg + start + (lane & (CHUNK - 1)));
    } else {
        cnt = N - start;
        #pragma unroll
        for (int j = 0; j < CHUNK; j++) {
            int n = min(start + j, N - 1);
            r[j] = __ldcs(hv4 + (size_t)n * 32 + lane);
        }
        segv = __ldg(seg + min(start + (lane & (CHUNK - 1)), N - 1));
    }

    const float4 wg4 = reinterpret_cast<const float4*>(Wg)[lane];
    const float4 w4  = reinterpret_cast<const float4*>(g_w)[lane];
    const float  bg0 = __ldg(bg);
    const float  c0l = g_c * (1.0f / 32.0f);   // distributed across lanes

    // per-node gate and lane-partial projection
    float gatev[CHUNK], d2Lv[CHUNK];
    #pragma unroll
    for (int j = 0; j < CHUNK; j++) {
        const float4 h = r[j];
        float d1 = h.x * wg4.x + h.y * wg4.y + h.z * wg4.z + h.w * wg4.w;
        d1 = warp_sum(d1);
        gatev[j] = __fdividef(1.0f, 1.0f + __expf(-(d1 + bg0)));
        d2Lv[j]  = h.x * w4.x + h.y * w4.y + h.z * w4.z + h.w * w4.w;
    }

    const int s_first = __shfl_sync(0xffffffffu, segv, 0);
    const int s_last  = __shfl_sync(0xffffffffu, segv, cnt - 1);

    if (s_first == s_last) {
        // fast path: whole chunk in one segment
        float accL = 0.0f;
        #pragma unroll
        for (int j = 0; j < CHUNK; j++)
            if (j < cnt) accL += gatev[j] * (d2Lv[j] + c0l);
        accL = warp_sum(accL);
        if (lane == 0) atomicAdd(&g_accum[s_first], accL);
    } else {
        // slow path: run-length aggregation over the chunk
        int   cur_seg = s_first;
        float accL    = 0.0f;
        #pragma unroll
        for (int j = 0; j < CHUNK; j++) {
            const int s_id = __shfl_sync(0xffffffffu, segv, j);
            if (j < cnt) {
                if (s_id != cur_seg) {
                    float red = warp_sum(accL);
                    if (lane == 0) atomicAdd(&g_accum[cur_seg], red);
                    accL    = 0.0f;
                    cur_seg = s_id;
                }
                accL += gatev[j] * (d2Lv[j] + c0l);
            }
        }
        float red = warp_sum(accL);
        if (lane == 0) atomicAdd(&g_accum[cur_seg], red);
    }
}

// ---------------------------------------------------------------------------
// Kernel 3: tiny combine. One thread per graph; resets g_accum for the next
// replay (it is zero at module load for the first call).
// ---------------------------------------------------------------------------
__global__ void __launch_bounds__(256)
dgmg_combine(const float* __restrict__ be,
             const int*   __restrict__ a,
             float*       __restrict__ out,
             int B) {
    const int b = blockIdx.x * blockDim.x + threadIdx.x;
    if (b >= B) return;
    float logit = g_accum[b] + g_src[b] + be[0];
    g_accum[b] = 0.0f;   // reset for next replay
    float x = (a[b] != 0) ? logit : -logit;
    float ls = (x >= 0.0f) ? -log1pf(__expf(-x)) : (x - log1pf(__expf(x)));
    out[b] = ls;
}

// ---------------------------------------------------------------------------
extern "C" void kernel_launch(void* const* d_in, const int* in_sizes, int n_in,
                              void* d_out, int out_size) {
    const float* hv       = (const float*)d_in[0];
    const float* Wg       = (const float*)d_in[1];
    const float* bg       = (const float*)d_in[2];
    const float* Wp       = (const float*)d_in[3];
    const float* bp       = (const float*)d_in[4];
    const float* We       = (const float*)d_in[5];
    const float* be       = (const float*)d_in[6];
    const int*   seg_ids  = (const int*)d_in[7];
    const int*   last_idx = (const int*)d_in[8];
    const int*   a        = (const int*)d_in[9];
    float* out = (float*)d_out;

    const int N = in_sizes[0] / D;
    const int B = in_sizes[8];

    // K1: fold weights (129 warps)
    dgmg_precompute<<<17, 256>>>(Wp, bp, We);

    // K2: src gather (head) + node stream, 8 warps/block, CHUNK=8
    const int nodeWarps  = (N + CHUNK - 1) / CHUNK;
    const int nodeBlocks = (nodeWarps + 7) / 8;
    const int srcBlocks  = (B + 7) / 8;
    dgmg_main<<<srcBlocks + nodeBlocks, 256>>>(hv, Wg, bg, seg_ids, We,
                                               last_idx, N, B, srcBlocks);

    // K3: combine
    dgmg_combine<<<(B + 255) / 256, 256>>>(be, a, out, B);
}